// round 4
// baseline (speedup 1.0000x reference)
#include <cuda_runtime.h>
#include <cuda_fp16.h>
#include <stdint.h>

#define C 64
#define NMAX 100000
#define EMAX 3200000

// ---------------------------------------------------------------------------
// Static scratch (no allocation allowed)
__device__ __align__(16) __half g_Fnh[(size_t)NMAX * C];  // F_n in fp16, [n][c]
__device__ __align__(16) float g_Fvt[(size_t)NMAX * C];   // F_v -> overwritten with pre-BN value
__device__ unsigned g_cnt[NMAX];        // degree histogram
__device__ unsigned g_off[NMAX];        // CSR offsets (exclusive scan of cnt)
__device__ unsigned g_cursor[NMAX];     // mutable cursors for CSR fill
__device__ unsigned g_blk[64];          // scan block totals
__device__ unsigned g_blkoff[64];       // scanned block offsets
__device__ int      g_csr[EMAX];        // CSR adjacency (gather_index sorted by dest)
__device__ float    g_csum[C];
__device__ float    g_csq[C];
__device__ float    g_wvT[C * C];       // w transposed [i][o]
__device__ float    g_wnT[C * C];

#define FMA2(acc, b, c) asm("fma.rn.f32x2 %0, %1, %2, %0;" : "+l"(acc) : "l"(b), "l"(c))

__device__ __forceinline__ unsigned h2_as_u32(__half2 h) {
    return *reinterpret_cast<unsigned*>(&h);
}

// ---------------------------------------------------------------------------
__global__ void transpose_w_kernel(const float* __restrict__ wv,
                                   const float* __restrict__ wn) {
    int k = blockIdx.x * blockDim.x + threadIdx.x;
    if (k < C * C) {
        int o = k >> 6, i = k & 63;
        g_wvT[i * C + o] = wv[k];
        g_wnT[i * C + o] = wn[k];
    }
}

// ---------------------------------------------------------------------------
__global__ void zero_kernel(int N) {
    int i = blockIdx.x * blockDim.x + threadIdx.x;
    if (i < N) g_cnt[i] = 0u;
    if (i < C) { g_csum[i] = 0.f; g_csq[i] = 0.f; }
}

// ---------------------------------------------------------------------------
// Dual 1x1 conv via packed fp32x2 FMA. Block: 256 threads, 64 nodes.
// Thread: 2 nodes x 8 channels x 2 matrices; accumulators pair adjacent channels.
__global__ void __launch_bounds__(256) gemm_kernel(const float* __restrict__ x, int N) {
    __shared__ __align__(16) float swv[C * C];  // [i][o]
    __shared__ __align__(16) float swn[C * C];  // [i][o]
    __shared__ __align__(16) float sx[C * 64];  // [i][node_local]

    int tid = threadIdx.x;
    int n0 = blockIdx.x * 64;

    for (int k = tid; k < C * C; k += 256) {
        swv[k] = g_wvT[k];
        swn[k] = g_wnT[k];
        int i = k >> 6, nl = k & 63;
        int n = n0 + nl;
        sx[k] = (n < N) ? x[(size_t)i * N + n] : 0.f;
    }
    __syncthreads();

    const int c0  = (tid & 7) * 8;   // channel base (8 consecutive channels)
    const int nl0 = (tid >> 3) * 2;  // node-pair base

    // acc[k] holds channels (c0+2k, c0+2k+1) packed as f32x2
    unsigned long long av0[4] = {0ull, 0ull, 0ull, 0ull};
    unsigned long long av1[4] = {0ull, 0ull, 0ull, 0ull};
    unsigned long long an0[4] = {0ull, 0ull, 0ull, 0ull};
    unsigned long long an1[4] = {0ull, 0ull, 0ull, 0ull};

#pragma unroll 8
    for (int i = 0; i < C; i++) {
        float2 xp = *reinterpret_cast<const float2*>(sx + i * 64 + nl0);
        unsigned long long x0d, x1d;
        asm("mov.b64 %0, {%1, %1};" : "=l"(x0d) : "f"(xp.x));
        asm("mov.b64 %0, {%1, %1};" : "=l"(x1d) : "f"(xp.y));

        const ulonglong2* wv2 = reinterpret_cast<const ulonglong2*>(swv + i * C + c0);
        const ulonglong2* wn2 = reinterpret_cast<const ulonglong2*>(swn + i * C + c0);
        ulonglong2 wva = wv2[0], wvb = wv2[1];
        ulonglong2 wna = wn2[0], wnb = wn2[1];

        FMA2(av0[0], wva.x, x0d); FMA2(av0[1], wva.y, x0d);
        FMA2(av0[2], wvb.x, x0d); FMA2(av0[3], wvb.y, x0d);
        FMA2(av1[0], wva.x, x1d); FMA2(av1[1], wva.y, x1d);
        FMA2(av1[2], wvb.x, x1d); FMA2(av1[3], wvb.y, x1d);
        FMA2(an0[0], wna.x, x0d); FMA2(an0[1], wna.y, x0d);
        FMA2(an0[2], wnb.x, x0d); FMA2(an0[3], wnb.y, x0d);
        FMA2(an1[0], wna.x, x1d); FMA2(an1[1], wna.y, x1d);
        FMA2(an1[2], wnb.x, x1d); FMA2(an1[3], wnb.y, x1d);
    }

    // unpack and store
    float v[8], w[8];
#pragma unroll
    for (int k = 0; k < 4; k++) {
        asm("mov.b64 {%0, %1}, %2;" : "=f"(v[2 * k]), "=f"(v[2 * k + 1]) : "l"(av0[k]));
        asm("mov.b64 {%0, %1}, %2;" : "=f"(w[2 * k]), "=f"(w[2 * k + 1]) : "l"(an0[k]));
    }
    int n_a = n0 + nl0;
    if (n_a < N) {
        float4* pv = reinterpret_cast<float4*>(g_Fvt + (size_t)n_a * C + c0);
        pv[0] = make_float4(v[0], v[1], v[2], v[3]);
        pv[1] = make_float4(v[4], v[5], v[6], v[7]);
        uint4 pk = make_uint4(h2_as_u32(__float22half2_rn(make_float2(w[0], w[1]))),
                              h2_as_u32(__float22half2_rn(make_float2(w[2], w[3]))),
                              h2_as_u32(__float22half2_rn(make_float2(w[4], w[5]))),
                              h2_as_u32(__float22half2_rn(make_float2(w[6], w[7]))));
        *reinterpret_cast<uint4*>(reinterpret_cast<char*>(g_Fnh) + ((size_t)n_a * C + c0) * 2) = pk;
    }
#pragma unroll
    for (int k = 0; k < 4; k++) {
        asm("mov.b64 {%0, %1}, %2;" : "=f"(v[2 * k]), "=f"(v[2 * k + 1]) : "l"(av1[k]));
        asm("mov.b64 {%0, %1}, %2;" : "=f"(w[2 * k]), "=f"(w[2 * k + 1]) : "l"(an1[k]));
    }
    int n_b = n_a + 1;
    if (n_b < N) {
        float4* pv = reinterpret_cast<float4*>(g_Fvt + (size_t)n_b * C + c0);
        pv[0] = make_float4(v[0], v[1], v[2], v[3]);
        pv[1] = make_float4(v[4], v[5], v[6], v[7]);
        uint4 pk = make_uint4(h2_as_u32(__float22half2_rn(make_float2(w[0], w[1]))),
                              h2_as_u32(__float22half2_rn(make_float2(w[2], w[3]))),
                              h2_as_u32(__float22half2_rn(make_float2(w[4], w[5]))),
                              h2_as_u32(__float22half2_rn(make_float2(w[6], w[7]))));
        *reinterpret_cast<uint4*>(reinterpret_cast<char*>(g_Fnh) + ((size_t)n_b * C + c0) * 2) = pk;
    }
}

// ---------------------------------------------------------------------------
// Degree histogram (vectorized index reads)
__global__ void __launch_bounds__(256) hist_kernel(const int* __restrict__ ridx, int E) {
    int t = blockIdx.x * 256 + threadIdx.x;
    int E4 = E >> 2;
    if (t < E4) {
        int4 r = reinterpret_cast<const int4*>(ridx)[t];
        atomicAdd(&g_cnt[r.x], 1u);
        atomicAdd(&g_cnt[r.y], 1u);
        atomicAdd(&g_cnt[r.z], 1u);
        atomicAdd(&g_cnt[r.w], 1u);
    } else if (t == E4) {
        for (int e = E4 * 4; e < E; e++) atomicAdd(&g_cnt[ridx[e]], 1u);
    }
}

// ---------------------------------------------------------------------------
// Scan pass 1: per-block (2048 elements) exclusive scan + block totals
__global__ void __launch_bounds__(256) scan1_kernel(int N) {
    __shared__ unsigned sdata[256];
    int t = threadIdx.x;
    int base = blockIdx.x * 2048 + t * 8;

    unsigned v[8];
#pragma unroll
    for (int k = 0; k < 8; k++) v[k] = (base + k < N) ? g_cnt[base + k] : 0u;
    unsigned run = 0;
#pragma unroll
    for (int k = 0; k < 8; k++) { unsigned c = v[k]; v[k] = run; run += c; }
    sdata[t] = run;
    __syncthreads();
    for (int off = 1; off < 256; off <<= 1) {
        unsigned y = (t >= off) ? sdata[t - off] : 0u;
        __syncthreads();
        sdata[t] += y;
        __syncthreads();
    }
    unsigned bexcl = (t > 0) ? sdata[t - 1] : 0u;
#pragma unroll
    for (int k = 0; k < 8; k++)
        if (base + k < N) g_off[base + k] = bexcl + v[k];
    if (t == 255) g_blk[blockIdx.x] = sdata[255];
}

__global__ void scan2_kernel(int nb) {
    __shared__ unsigned s[64];
    int t = threadIdx.x;
    s[t] = (t < nb) ? g_blk[t] : 0u;
    __syncthreads();
    for (int off = 1; off < 64; off <<= 1) {
        unsigned y = (t >= off) ? s[t - off] : 0u;
        __syncthreads();
        s[t] += y;
        __syncthreads();
    }
    g_blkoff[t] = (t > 0) ? s[t - 1] : 0u;
}

__global__ void __launch_bounds__(256) scan3_kernel(int N) {
    int i = blockIdx.x * 256 + threadIdx.x;
    if (i < N) {
        unsigned o = g_off[i] + g_blkoff[i >> 11];
        g_off[i] = o;
        g_cursor[i] = o;
    }
}

// ---------------------------------------------------------------------------
// CSR fill (vectorized index reads)
__global__ void __launch_bounds__(256) csr_kernel(const int* __restrict__ ridx,
                                                  const int* __restrict__ gidx, int E) {
    int t = blockIdx.x * 256 + threadIdx.x;
    int E4 = E >> 2;
    if (t < E4) {
        int4 r = reinterpret_cast<const int4*>(ridx)[t];
        int4 g = reinterpret_cast<const int4*>(gidx)[t];
        g_csr[atomicAdd(&g_cursor[r.x], 1u)] = g.x;
        g_csr[atomicAdd(&g_cursor[r.y], 1u)] = g.y;
        g_csr[atomicAdd(&g_cursor[r.z], 1u)] = g.z;
        g_csr[atomicAdd(&g_cursor[r.w], 1u)] = g.w;
    } else if (t == E4) {
        for (int e = E4 * 4; e < E; e++)
            g_csr[atomicAdd(&g_cursor[ridx[e]], 1u)] = gidx[e];
    }
}

// ---------------------------------------------------------------------------
// Per-node segmented gather-sum over fp16 F_n -> mean + F_v (fp32), BN stats.
// One warp per node; lane j (0..7) owns channels 8j..8j+7; h=lane>>3 splits edges 4-way.
__global__ void __launch_bounds__(256) nodered_kernel(int N, int E) {
    __shared__ float ssum[C];
    __shared__ float ssq[C];
    int tid = threadIdx.x;
    if (tid < C) { ssum[tid] = 0.f; ssq[tid] = 0.f; }
    __syncthreads();

    int lane = tid & 31, wid = tid >> 5;
    int j = lane & 7, h = lane >> 3;
    int warps = gridDim.x * 8;
    int gw = blockIdx.x * 8 + wid;

    float s[8], q[8];
#pragma unroll
    for (int k = 0; k < 8; k++) { s[k] = 0.f; q[k] = 0.f; }

    const uint4* Fn4 = reinterpret_cast<const uint4*>(g_Fnh);

    for (int n = gw; n < N; n += warps) {
        unsigned start = g_off[n];
        unsigned end = (n + 1 < N) ? g_off[n + 1] : (unsigned)E;
        float a[8];
#pragma unroll
        for (int k = 0; k < 8; k++) a[k] = 0.f;

        for (unsigned ei = start + h; ei < end; ei += 4) {
            int src = g_csr[ei];
            uint4 p = __ldg(Fn4 + (size_t)src * 8 + j);
            float2 f0 = __half22float2(*reinterpret_cast<__half2*>(&p.x));
            float2 f1 = __half22float2(*reinterpret_cast<__half2*>(&p.y));
            float2 f2 = __half22float2(*reinterpret_cast<__half2*>(&p.z));
            float2 f3 = __half22float2(*reinterpret_cast<__half2*>(&p.w));
            a[0] += f0.x; a[1] += f0.y; a[2] += f1.x; a[3] += f1.y;
            a[4] += f2.x; a[5] += f2.y; a[6] += f3.x; a[7] += f3.y;
        }
        // merge 4 half-warp partials (h dimension)
#pragma unroll
        for (int k = 0; k < 8; k++) {
            a[k] += __shfl_xor_sync(0xffffffffu, a[k], 8);
            a[k] += __shfl_xor_sync(0xffffffffu, a[k], 16);
        }

        if (h == 0) {
            float inv = 1.f / fmaxf((float)(end - start), 1.f);
            float4* p = reinterpret_cast<float4*>(g_Fvt + (size_t)n * C + j * 8);
            float4 fv0 = p[0], fv1 = p[1];
            float v0 = a[0] * inv + fv0.x;
            float v1 = a[1] * inv + fv0.y;
            float v2 = a[2] * inv + fv0.z;
            float v3 = a[3] * inv + fv0.w;
            float v4 = a[4] * inv + fv1.x;
            float v5 = a[5] * inv + fv1.y;
            float v6 = a[6] * inv + fv1.z;
            float v7 = a[7] * inv + fv1.w;
            p[0] = make_float4(v0, v1, v2, v3);
            p[1] = make_float4(v4, v5, v6, v7);
            s[0] += v0; s[1] += v1; s[2] += v2; s[3] += v3;
            s[4] += v4; s[5] += v5; s[6] += v6; s[7] += v7;
            q[0] += v0 * v0; q[1] += v1 * v1; q[2] += v2 * v2; q[3] += v3 * v3;
            q[4] += v4 * v4; q[5] += v5 * v5; q[6] += v6 * v6; q[7] += v7 * v7;
        }
    }

    if (h == 0) {
        int cb = j * 8;
#pragma unroll
        for (int k = 0; k < 8; k++) {
            atomicAdd(&ssum[cb + k], s[k]);
            atomicAdd(&ssq[cb + k], q[k]);
        }
    }
    __syncthreads();
    if (tid < C) {
        atomicAdd(&g_csum[tid], ssum[tid]);
        atomicAdd(&g_csq[tid], ssq[tid]);
    }
}

// ---------------------------------------------------------------------------
// BN normalize + affine + PReLU + transpose [n][c] -> out [c][n]
__global__ void __launch_bounds__(256) bnfinal_kernel(float* __restrict__ out,
                                                      const float* __restrict__ gamma,
                                                      const float* __restrict__ beta,
                                                      const float* __restrict__ prelu,
                                                      int N) {
    __shared__ float tile[64][65];
    int tid = threadIdx.x;
    int n0 = blockIdx.x * 64;

    int c = tid & 63;
    int nrow0 = tid >> 6;

    float invN = 1.0f / (float)N;
    float mu = g_csum[c] * invN;
    float var = g_csq[c] * invN - mu * mu;
    float scale = rsqrtf(var + 1e-5f) * gamma[c];
    float shift = beta[c] - mu * scale;
    float a = prelu[0];

#pragma unroll
    for (int m = 0; m < 16; m++) {
        int nl = nrow0 + m * 4;
        int n = n0 + nl;
        float v = 0.f;
        if (n < N) {
            v = g_Fvt[(size_t)n * C + c] * scale + shift;
            v = (v >= 0.f) ? v : a * v;
        }
        tile[c][nl] = v;
    }
    __syncthreads();

    int nl = tid & 63;
    int c2b = tid >> 6;
    if (n0 + nl < N) {
#pragma unroll
        for (int m = 0; m < 16; m++) {
            int c2 = c2b + m * 4;
            out[(size_t)c2 * N + n0 + nl] = tile[c2][nl];
        }
    }
}

// ---------------------------------------------------------------------------
extern "C" void kernel_launch(void* const* d_in, const int* in_sizes, int n_in,
                              void* d_out, int out_size) {
    const float* x     = (const float*)d_in[0];  // [64, N]
    const float* wv    = (const float*)d_in[1];  // [64, 64]
    const float* wn    = (const float*)d_in[2];  // [64, 64]
    const float* gamma = (const float*)d_in[3];
    const float* beta  = (const float*)d_in[4];
    const float* prelu = (const float*)d_in[5];
    const int*   ridx  = (const int*)d_in[6];    // reduce_index [E]
    const int*   gidx  = (const int*)d_in[7];    // gather_index [E]
    float* out = (float*)d_out;

    int N = in_sizes[0] / C;
    int E = in_sizes[6];
    if (N > NMAX) N = NMAX;
    if (E > EMAX) E = EMAX;

    transpose_w_kernel<<<(C * C + 255) / 256, 256>>>(wv, wn);
    zero_kernel<<<(N + 255) / 256, 256>>>(N);
    gemm_kernel<<<(N + 63) / 64, 256>>>(x, N);

    int E4 = E >> 2;
    hist_kernel<<<(E4 + 256) / 256, 256>>>(ridx, E);

    int nb = (N + 2047) / 2048;
    scan1_kernel<<<nb, 256>>>(N);
    scan2_kernel<<<1, 64>>>(nb);
    scan3_kernel<<<(N + 255) / 256, 256>>>(N);

    csr_kernel<<<(E4 + 256) / 256, 256>>>(ridx, gidx, E);

    nodered_kernel<<<1184, 256>>>(N, E);

    bnfinal_kernel<<<(N + 63) / 64, 256>>>(out, gamma, beta, prelu, N);
}